// round 1
// baseline (speedup 1.0000x reference)
#include <cuda_runtime.h>
#include <math.h>

#define N_TOK   49
#define C_DIM   96
#define H_NUM   3
#define HD      32
#define PAIRS   (N_TOK * H_NUM)   // 147
#define THREADS 160

// MLP-generated relative position bias, shared by all windows: [H][N][N]
__device__ float g_bias[H_NUM * N_TOK * N_TOK];

// ---------------------------------------------------------------------------
// Kernel 1: bias = relu(rel_pos @ w1 + b1) @ w2 + b2    (2401 positions)
// rel_pos: [N*N, 2], w1: [2,256], b1: [256], w2: [256,3], b2: [3]
// ---------------------------------------------------------------------------
__global__ void bias_kernel(const float* __restrict__ rel_pos,
                            const float* __restrict__ w1,
                            const float* __restrict__ b1,
                            const float* __restrict__ w2,
                            const float* __restrict__ b2) {
    int p = blockIdx.x * blockDim.x + threadIdx.x;
    if (p >= N_TOK * N_TOK) return;
    float r0 = rel_pos[p * 2 + 0];
    float r1 = rel_pos[p * 2 + 1];
    float acc0 = b2[0], acc1 = b2[1], acc2 = b2[2];
    #pragma unroll 8
    for (int j = 0; j < 256; ++j) {
        float hj = fmaf(r0, w1[j], fmaf(r1, w1[256 + j], b1[j]));
        hj = fmaxf(hj, 0.0f);
        acc0 = fmaf(hj, w2[j * 3 + 0], acc0);
        acc1 = fmaf(hj, w2[j * 3 + 1], acc1);
        acc2 = fmaf(hj, w2[j * 3 + 2], acc2);
    }
    g_bias[0 * (N_TOK * N_TOK) + p] = acc0;
    g_bias[1 * (N_TOK * N_TOK) + p] = acc1;
    g_bias[2 * (N_TOK * N_TOK) + p] = acc2;
}

// ---------------------------------------------------------------------------
// Kernel 2: window attention. One CTA per window.
// Thread t -> pair (h = t/49, n = t%49) for t < 147.
// k, v staged in smem; q read directly (128B-segment tiling, each sector once).
// ---------------------------------------------------------------------------
__global__ __launch_bounds__(THREADS)
void attn_kernel(const float* __restrict__ q,
                 const float* __restrict__ k,
                 const float* __restrict__ v,
                 float*       __restrict__ out) {
    __shared__ float ks[N_TOK * C_DIM];
    __shared__ float vs[N_TOK * C_DIM];

    const int b = blockIdx.x;
    const int t = threadIdx.x;
    const size_t wbase = (size_t)b * (N_TOK * C_DIM);

    // cooperative float4 staging of k and v (4704 floats each = 1176 float4)
    {
        const float4* k4 = (const float4*)(k + wbase);
        const float4* v4 = (const float4*)(v + wbase);
        float4* ks4 = (float4*)ks;
        float4* vs4 = (float4*)vs;
        #pragma unroll
        for (int i = t; i < (N_TOK * C_DIM) / 4; i += THREADS) {
            ks4[i] = k4[i];
            vs4[i] = v4[i];
        }
    }
    __syncthreads();

    if (t < PAIRS) {
        const int h = t / N_TOK;
        const int n = t - h * N_TOK;

        // load this thread's query row (32 floats)
        float qreg[HD];
        {
            const float* qp = q + wbase + n * C_DIM + h * HD;
            #pragma unroll
            for (int d = 0; d < HD; d += 4) {
                float4 x = *(const float4*)(qp + d);
                qreg[d + 0] = x.x; qreg[d + 1] = x.y;
                qreg[d + 2] = x.z; qreg[d + 3] = x.w;
            }
        }

        const float scale = 0.17677669529663687f;  // 1/sqrt(32)
        const float* bp = g_bias + (h * N_TOK + n) * N_TOK;

        float s[N_TOK];
        float mx = -1e30f;
        #pragma unroll
        for (int m = 0; m < N_TOK; ++m) {
            const float* kp = ks + m * C_DIM + h * HD;
            float acc = 0.0f;
            #pragma unroll
            for (int d = 0; d < HD; ++d)
                acc = fmaf(qreg[d], kp[d], acc);
            acc = fmaf(acc, scale, __ldg(bp + m));
            s[m] = acc;
            mx = fmaxf(mx, acc);
        }

        float sum = 0.0f;
        #pragma unroll
        for (int m = 0; m < N_TOK; ++m) {
            float e = __expf(s[m] - mx);
            s[m] = e;
            sum += e;
        }
        const float inv = 1.0f / sum;

        float o[HD];
        #pragma unroll
        for (int d = 0; d < HD; ++d) o[d] = 0.0f;
        #pragma unroll
        for (int m = 0; m < N_TOK; ++m) {
            const float p = s[m] * inv;
            const float* vp = vs + m * C_DIM + h * HD;
            #pragma unroll
            for (int d = 0; d < HD; ++d)
                o[d] = fmaf(p, vp[d], o[d]);
        }

        float* op = out + wbase + n * C_DIM + h * HD;
        #pragma unroll
        for (int d = 0; d < HD; d += 4) {
            float4 x = make_float4(o[d], o[d + 1], o[d + 2], o[d + 3]);
            *(float4*)(op + d) = x;
        }
    }
}

// ---------------------------------------------------------------------------
extern "C" void kernel_launch(void* const* d_in, const int* in_sizes, int n_in,
                              void* d_out, int out_size) {
    const float* q       = (const float*)d_in[0];
    const float* k       = (const float*)d_in[1];
    const float* v       = (const float*)d_in[2];
    const float* rel_pos = (const float*)d_in[3];
    const float* w1      = (const float*)d_in[4];
    const float* b1      = (const float*)d_in[5];
    const float* w2      = (const float*)d_in[6];
    const float* b2      = (const float*)d_in[7];
    float* out = (float*)d_out;

    const int nwin = in_sizes[0] / (N_TOK * C_DIM);

    bias_kernel<<<(N_TOK * N_TOK + 127) / 128, 128>>>(rel_pos, w1, b1, w2, b2);
    attn_kernel<<<nwin, THREADS>>>(q, k, v, out);
}